// round 4
// baseline (speedup 1.0000x reference)
#include <cuda_runtime.h>
#include <math.h>

#define HH 1024
#define WW 1024
#define NPIX (HH * WW)
#define NWORDS (WW / 32)              // 32 packed words per row
#define COL_BLOCK 256
#define COL_GRID (NPIX / COL_BLOCK)   // 4096 blocks per image
#define TOT_COL_BLOCKS (2 * COL_GRID)

// Scratch (no allocations allowed anywhere)
__device__ unsigned int g_edgebits[2][HH * NWORDS];   // 256 KB: edge masks, 1 bit/pixel
__device__ float        g_g2[2][NPIX];                // 8 MB: squared row distances
__device__ float        g_blockSums[TOT_COL_BLOCKS];
__device__ unsigned int g_count;                      // zero-init at load; reset by kernel A

// ---------------------------------------------------------------------------
// Kernel A: bit-packed edges + per-row 1D distance.
// One block per (row, image); 1024 threads = one per column.
//   - 3 coalesced float loads/thread (rows i-1, i, i+1), ballot-packed to bits
//   - erosion = AND of 3 horizontally-ANDed row words (funnel shifts handle
//     word boundaries; zero carries give eroded=0 at image borders for free)
//   - row distance via __clz/__ffs on the packed edge words (exact),
//     with the reference's 1e6 defaults replicated exactly in fp32
// ---------------------------------------------------------------------------
__global__ void __launch_bounds__(WW) edges_rowdist_kernel(
    const float* __restrict__ preds, const float* __restrict__ targets)
{
    const int i = blockIdx.x;       // row
    const int m = blockIdx.y;       // image
    const int j = threadIdx.x;      // column
    const float* __restrict__ seg = (m == 0) ? preds : targets;

    // reset the colpass completion counter for this replay
    if (i == 0 && m == 0 && j == 0) g_count = 0u;

    __shared__ unsigned int shP[NWORDS], shC[NWORDS], shN[NWORDS], shE[NWORDS];

    const float cv = seg[i * WW + j];
    const float pv = (i > 0)      ? seg[(i - 1) * WW + j] : 0.0f;
    const float nv = (i < HH - 1) ? seg[(i + 1) * WW + j] : 0.0f;

    const unsigned bc = __ballot_sync(0xffffffffu, cv == 1.0f);
    const unsigned bp = __ballot_sync(0xffffffffu, pv == 1.0f);
    const unsigned bn = __ballot_sync(0xffffffffu, nv == 1.0f);

    const int t = j >> 5, k = j & 31;
    if (k == 0) { shP[t] = bp; shC[t] = bc; shN[t] = bn; }
    __syncthreads();

    // 32 threads compute one edge word each
    if (j < NWORDS) {
        const int w = j;
        unsigned er = 0u;
        if (i > 0 && i < HH - 1) {
            unsigned hp, hc, hn;
            {
                const unsigned wv = shP[w];
                const unsigned wl = (w > 0)          ? shP[w - 1] : 0u;
                const unsigned wr = (w < NWORDS - 1) ? shP[w + 1] : 0u;
                hp = wv & ((wv << 1) | (wl >> 31)) & ((wv >> 1) | (wr << 31));
            }
            {
                const unsigned wv = shC[w];
                const unsigned wl = (w > 0)          ? shC[w - 1] : 0u;
                const unsigned wr = (w < NWORDS - 1) ? shC[w + 1] : 0u;
                hc = wv & ((wv << 1) | (wl >> 31)) & ((wv >> 1) | (wr << 31));
            }
            {
                const unsigned wv = shN[w];
                const unsigned wl = (w > 0)          ? shN[w - 1] : 0u;
                const unsigned wr = (w < NWORDS - 1) ? shN[w + 1] : 0u;
                hn = wv & ((wv << 1) | (wl >> 31)) & ((wv >> 1) | (wr << 31));
            }
            er = hp & hc & hn;
        }
        const unsigned e = shC[w] & ~er;   // edges = seg & ~eroded
        shE[w] = e;
        g_edgebits[m][i * NWORDS + w] = e;
    }
    __syncthreads();

    // ---- per-pixel nearest edge bit in this row ----
    const unsigned ew = shE[t];
    float g;
    if ((ew >> k) & 1u) {
        g = 0.0f;
    } else {
        // left side (bits < k in word t, then earlier words)
        float dl;
        const unsigned lw = (k > 0) ? (ew & ((1u << k) - 1u)) : 0u;
        if (lw) {
            dl = (float)(k - (31 - __clz(lw)));
        } else {
            int tt = t - 1;
            while (tt >= 0 && shE[tt] == 0u) tt--;
            if (tt >= 0) {
                const int pos = tt * 32 + (31 - __clz(shE[tt]));
                dl = (float)(j - pos);
            } else {
                dl = (float)j + 1e6f;              // reference default (exact fp32)
            }
        }
        // right side (bits > k in word t, then later words)
        float dr;
        const unsigned rw = (k < 31) ? (ew & (0xFFFFFFFEu << k)) : 0u;
        if (rw) {
            dr = (float)(__ffs(rw) - 1 - k);
        } else {
            int tt = t + 1;
            while (tt < NWORDS && shE[tt] == 0u) tt++;
            if (tt < NWORDS) {
                const int pos = tt * 32 + (__ffs(shE[tt]) - 1);
                dr = (float)(pos - j);
            } else {
                dr = 1e6f - (float)j;              // reference default (exact fp32)
            }
        }
        g = fminf(fminf(dl, dr), 1e6f);
    }
    g_g2[m][i * WW + j] = g * g;
}

// ---------------------------------------------------------------------------
// Kernel B: column lower-envelope (exact, pruned) + masked sum, with the
// final reduction fused via the threadfence / last-block-counter pattern.
// D2[i][j] = min_k g2[k][j] + (i-k)^2; once d^2 >= best, no farther row can
// improve (g2 >= 0) -> exact early exit. Only evaluated where the OTHER
// image's edge bit is set (the weight). Deterministic reduction order.
// ---------------------------------------------------------------------------
__global__ void __launch_bounds__(COL_BLOCK) colpass_kernel(float* __restrict__ out)
{
    const int p = blockIdx.x * COL_BLOCK + threadIdx.x;   // pixel index
    const int m = blockIdx.y;                             // image whose DT we take

    float contrib = 0.0f;
    const unsigned maskw = g_edgebits[1 - m][p >> 5];
    if ((maskw >> (p & 31)) & 1u) {
        const float* __restrict__ g2 = g_g2[m];
        float best = g2[p];
        for (int d = 1; ; d++) {
            const float dd = (float)(d * d);      // exact for d <= 1024
            if (dd >= best) break;                // provably cannot improve
            const int up = p - d * WW;
            const int dn = p + d * WW;
            if (up >= 0)   best = fminf(best, g2[up] + dd);
            if (dn < NPIX) best = fminf(best, g2[dn] + dd);
            if (up < 0 && dn >= NPIX) break;
        }
        contrib = sqrtf(best);
    }

    // deterministic in-block reduction
    float v = contrib;
    #pragma unroll
    for (int o = 16; o > 0; o >>= 1) v += __shfl_down_sync(0xffffffffu, v, o);

    __shared__ float warpsum[COL_BLOCK / 32];
    __shared__ bool  isLast;
    if ((threadIdx.x & 31) == 0) warpsum[threadIdx.x >> 5] = v;
    __syncthreads();

    if (threadIdx.x < (COL_BLOCK / 32)) {
        float w = warpsum[threadIdx.x];
        #pragma unroll
        for (int o = (COL_BLOCK / 64); o > 0; o >>= 1)
            w += __shfl_down_sync(0xffu, w, o);
        if (threadIdx.x == 0) {
            g_blockSums[m * COL_GRID + blockIdx.x] = w;
            __threadfence();
            const unsigned old = atomicAdd(&g_count, 1u);
            isLast = (old == TOT_COL_BLOCKS - 1);
        }
    }
    __syncthreads();

    // last block to finish performs the (deterministic, fixed-order) final sum
    if (isLast) {
        __threadfence();
        float s = 0.0f;
        for (int q = threadIdx.x; q < TOT_COL_BLOCKS; q += COL_BLOCK)
            s += g_blockSums[q];

        __shared__ float sh[COL_BLOCK];
        sh[threadIdx.x] = s;
        __syncthreads();
        #pragma unroll
        for (int stride = COL_BLOCK / 2; stride > 0; stride >>= 1) {
            if (threadIdx.x < stride) sh[threadIdx.x] += sh[threadIdx.x + stride];
            __syncthreads();
        }
        if (threadIdx.x == 0) {
            const float loss = sh[0] / (2.0f * (float)NPIX);
            out[0] = 1.0f / (1.0f + expf(-loss));
        }
    }
}

// ---------------------------------------------------------------------------
extern "C" void kernel_launch(void* const* d_in, const int* in_sizes, int n_in,
                              void* d_out, int out_size)
{
    const float* preds   = (const float*)d_in[0];
    const float* targets = (const float*)d_in[1];
    float* out = (float*)d_out;
    (void)in_sizes; (void)n_in; (void)out_size;

    dim3 gridA(HH, 2);
    edges_rowdist_kernel<<<gridA, WW>>>(preds, targets);

    dim3 gridB(COL_GRID, 2);
    colpass_kernel<<<gridB, COL_BLOCK>>>(out);
}

// round 5
// speedup vs baseline: 1.0631x; 1.0631x over previous
#include <cuda_runtime.h>
#include <math.h>

#define HH 1024
#define WW 1024
#define NPIX (HH * WW)
#define NWORDS (WW / 32)              // 32 packed words per row
#define RPB 4                         // rows per block in kernel A
#define COL_BLOCK 256
#define COL_GRID (NPIX / COL_BLOCK)   // 4096 blocks per image
#define TOT_COL_BLOCKS (2 * COL_GRID)

// Scratch (no allocations allowed anywhere)
__device__ unsigned int g_edgebits[2][HH * NWORDS];   // 256 KB
__device__ float        g_g2[2][NPIX];                // 8 MB
__device__ float        g_blockSums[TOT_COL_BLOCKS];

__device__ __forceinline__ unsigned horiz3(unsigned wv, unsigned wl, unsigned wr) {
    // horizontal 3-wide AND with word-boundary carries
    return wv & ((wv << 1) | (wl >> 31)) & ((wv >> 1) | (wr << 31));
}

// ---------------------------------------------------------------------------
// Kernel A: bit-packed edges + per-row 1D distance, RPB rows per block.
// Loads RPB+2 rows (zero-padded at image borders -> erosion correct for free),
// ballots them to bit rows, computes RPB edge rows, then per-pixel nearest
// edge bit via clz/ffs with the reference's exact 1e6 fp32 defaults.
// ---------------------------------------------------------------------------
__global__ void __launch_bounds__(WW) edges_rowdist_kernel(
    const float* __restrict__ preds, const float* __restrict__ targets)
{
    const int r0 = blockIdx.x * RPB;
    const int m  = blockIdx.y;
    const int j  = threadIdx.x;
    const float* __restrict__ seg = (m == 0) ? preds : targets;

    __shared__ unsigned shB[RPB + 2][NWORDS];
    __shared__ unsigned shE[RPB][NWORDS];

    const int t = j >> 5, k = j & 31;

    // load RPB+2 rows (batched for MLP), ballot-pack
    float v[RPB + 2];
    #pragma unroll
    for (int rr = 0; rr < RPB + 2; rr++) {
        const int row = r0 + rr - 1;
        v[rr] = (row >= 0 && row < HH) ? seg[row * WW + j] : 0.0f;
    }
    #pragma unroll
    for (int rr = 0; rr < RPB + 2; rr++) {
        const unsigned b = __ballot_sync(0xffffffffu, v[rr] == 1.0f);
        if (k == 0) shB[rr][t] = b;
    }
    __syncthreads();

    // RPB*NWORDS = 128 threads compute one edge word each
    if (j < RPB * NWORDS) {
        const int w  = j & (NWORDS - 1);
        const int rr = j >> 5;            // NWORDS == 32
        unsigned hp, hc, hn;
        {
            const unsigned wv = shB[rr][w];
            hp = horiz3(wv, w > 0 ? shB[rr][w - 1] : 0u,
                            w < NWORDS - 1 ? shB[rr][w + 1] : 0u);
        }
        {
            const unsigned wv = shB[rr + 1][w];
            hc = horiz3(wv, w > 0 ? shB[rr + 1][w - 1] : 0u,
                            w < NWORDS - 1 ? shB[rr + 1][w + 1] : 0u);
        }
        {
            const unsigned wv = shB[rr + 2][w];
            hn = horiz3(wv, w > 0 ? shB[rr + 2][w - 1] : 0u,
                            w < NWORDS - 1 ? shB[rr + 2][w + 1] : 0u);
        }
        const unsigned e = shB[rr + 1][w] & ~(hp & hc & hn);
        shE[rr][w] = e;
        g_edgebits[m][(r0 + rr) * NWORDS + w] = e;
    }
    __syncthreads();

    // per-pixel nearest edge bit in each of the RPB rows
    #pragma unroll
    for (int rr = 0; rr < RPB; rr++) {
        const unsigned ew = shE[rr][t];
        float g;
        if ((ew >> k) & 1u) {
            g = 0.0f;
        } else {
            float dl;
            const unsigned lw = (k > 0) ? (ew & ((1u << k) - 1u)) : 0u;
            if (lw) {
                dl = (float)(k - (31 - __clz(lw)));
            } else {
                int tt = t - 1;
                while (tt >= 0 && shE[rr][tt] == 0u) tt--;
                if (tt >= 0) dl = (float)(j - (tt * 32 + (31 - __clz(shE[rr][tt]))));
                else         dl = (float)j + 1e6f;      // reference default, exact fp32
            }
            float dr;
            const unsigned rw = (k < 31) ? (ew & (0xFFFFFFFEu << k)) : 0u;
            if (rw) {
                dr = (float)(__ffs(rw) - 1 - k);
            } else {
                int tt = t + 1;
                while (tt < NWORDS && shE[rr][tt] == 0u) tt++;
                if (tt < NWORDS) dr = (float)((tt * 32 + (__ffs(shE[rr][tt]) - 1)) - j);
                else             dr = 1e6f - (float)j;  // reference default, exact fp32
            }
            g = fminf(fminf(dl, dr), 1e6f);
        }
        g_g2[m][(r0 + rr) * WW + j] = g * g;
    }
}

// ---------------------------------------------------------------------------
// Kernel B: column lower-envelope, batched 4 deep for MLP.
// All candidates g2[k]+(i-k)^2 are >= the true min, so evaluating extras is
// exact; the d^2 >= best test remains a provably-safe early exit.
// Only evaluated where the OTHER image's edge bit is set. No fences/atomics.
// ---------------------------------------------------------------------------
__global__ void __launch_bounds__(COL_BLOCK) colpass_kernel()
{
    const int p = blockIdx.x * COL_BLOCK + threadIdx.x;
    const int m = blockIdx.y;

    float contrib = 0.0f;
    const unsigned maskw = g_edgebits[1 - m][p >> 5];
    if ((maskw >> (p & 31)) & 1u) {
        const float* __restrict__ g2 = g_g2[m];
        float best = g2[p];
        if (best > 1.0f) {                      // same as d=1 prune in scalar form
            const int i       = p >> 10;        // WW == 1024
            const int dmax_up = i;
            const int dmax_dn = (HH - 1) - i;
            int d = 1;
            while (true) {
                float cand[4];
                #pragma unroll
                for (int q = 0; q < 4; q++) {
                    const int   dd  = d + q;
                    const float ddf = (float)(dd * dd);          // exact for dd <= 1024
                    const float vu = (dd <= dmax_up) ? g2[p - dd * WW] : 3e37f;
                    const float vd = (dd <= dmax_dn) ? g2[p + dd * WW] : 3e37f;
                    cand[q] = fminf(vu, vd) + ddf;
                }
                best = fminf(best,
                       fminf(fminf(cand[0], cand[1]), fminf(cand[2], cand[3])));
                d += 4;
                if ((float)(d * d) >= best) break;               // exact prune
                if (d > dmax_up && d > dmax_dn) break;           // scanned all rows
            }
        }
        contrib = sqrtf(best);
    }

    // deterministic in-block reduction
    float s = contrib;
    #pragma unroll
    for (int o = 16; o > 0; o >>= 1) s += __shfl_down_sync(0xffffffffu, s, o);

    __shared__ float warpsum[COL_BLOCK / 32];
    if ((threadIdx.x & 31) == 0) warpsum[threadIdx.x >> 5] = s;
    __syncthreads();

    if (threadIdx.x < (COL_BLOCK / 32)) {
        float w = warpsum[threadIdx.x];
        #pragma unroll
        for (int o = (COL_BLOCK / 64); o > 0; o >>= 1)
            w += __shfl_down_sync(0xffu, w, o);
        if (threadIdx.x == 0)
            g_blockSums[m * COL_GRID + blockIdx.x] = w;
    }
}

// ---------------------------------------------------------------------------
// Kernel C: deterministic final reduction + sigmoid.
// ---------------------------------------------------------------------------
__global__ void __launch_bounds__(1024) finalize_kernel(float* __restrict__ out)
{
    __shared__ float sh[1024];
    float s = 0.0f;
    for (int q = threadIdx.x; q < TOT_COL_BLOCKS; q += 1024) s += g_blockSums[q];
    sh[threadIdx.x] = s;
    __syncthreads();
    #pragma unroll
    for (int stride = 512; stride > 0; stride >>= 1) {
        if (threadIdx.x < stride) sh[threadIdx.x] += sh[threadIdx.x + stride];
        __syncthreads();
    }
    if (threadIdx.x == 0) {
        const float loss = sh[0] / (2.0f * (float)NPIX);
        out[0] = 1.0f / (1.0f + expf(-loss));
    }
}

// ---------------------------------------------------------------------------
extern "C" void kernel_launch(void* const* d_in, const int* in_sizes, int n_in,
                              void* d_out, int out_size)
{
    const float* preds   = (const float*)d_in[0];
    const float* targets = (const float*)d_in[1];
    float* out = (float*)d_out;
    (void)in_sizes; (void)n_in; (void)out_size;

    dim3 gridA(HH / RPB, 2);
    edges_rowdist_kernel<<<gridA, WW>>>(preds, targets);

    dim3 gridB(COL_GRID, 2);
    colpass_kernel<<<gridB, COL_BLOCK>>>();

    finalize_kernel<<<1, 1024>>>(out);
}

// round 6
// speedup vs baseline: 1.8816x; 1.7699x over previous
#include <cuda_runtime.h>
#include <math.h>

#define HH 1024
#define WW 1024
#define NPIX (HH * WW)
#define NWORDS (WW / 32)          // 32 packed words per row
#define RPB 8                     // rows per block in kernel A

// kernel B tiling
#define CTILE 32                  // columns per block (one mask word)
#define RTILE 256                 // rows per block
#define HALO  32                  // guaranteed in-shared scan band
#define SROWS (RTILE + 2 * HALO)  // 320 shared rows
#define NB_C (WW / CTILE)         // 32
#define NB_R (HH / RTILE)         // 4
#define TOT_B_BLOCKS (NB_C * NB_R * 2)   // 256

// Scratch (no allocations allowed anywhere)
__device__ unsigned int g_edgebits[2][HH * NWORDS];   // 256 KB
__device__ float        g_g2[2][NPIX];                // 8 MB
__device__ float        g_blockSums[TOT_B_BLOCKS];

__device__ __forceinline__ unsigned horiz3(unsigned wv, unsigned wl, unsigned wr) {
    return wv & ((wv << 1) | (wl >> 31)) & ((wv >> 1) | (wr << 31));
}

// ---------------------------------------------------------------------------
// Kernel A: bit-packed edges + per-row 1D distance, RPB rows per block.
// ---------------------------------------------------------------------------
__global__ void __launch_bounds__(WW) edges_rowdist_kernel(
    const float* __restrict__ preds, const float* __restrict__ targets)
{
    const int r0 = blockIdx.x * RPB;
    const int m  = blockIdx.y;
    const int j  = threadIdx.x;
    const float* __restrict__ seg = (m == 0) ? preds : targets;

    __shared__ unsigned shB[RPB + 2][NWORDS];
    __shared__ unsigned shE[RPB][NWORDS];

    const int t = j >> 5, k = j & 31;

    // load RPB+2 rows (batched for MLP), ballot-pack to bits
    float v[RPB + 2];
    #pragma unroll
    for (int rr = 0; rr < RPB + 2; rr++) {
        const int row = r0 + rr - 1;
        v[rr] = (row >= 0 && row < HH) ? seg[row * WW + j] : 0.0f;
    }
    #pragma unroll
    for (int rr = 0; rr < RPB + 2; rr++) {
        const unsigned b = __ballot_sync(0xffffffffu, v[rr] == 1.0f);
        if (k == 0) shB[rr][t] = b;
    }
    __syncthreads();

    // RPB*NWORDS = 256 threads compute one edge word each
    if (j < RPB * NWORDS) {
        const int w  = j & (NWORDS - 1);
        const int rr = j >> 5;            // NWORDS == 32
        const unsigned hp = horiz3(shB[rr][w],
                                   w > 0 ? shB[rr][w - 1] : 0u,
                                   w < NWORDS - 1 ? shB[rr][w + 1] : 0u);
        const unsigned hc = horiz3(shB[rr + 1][w],
                                   w > 0 ? shB[rr + 1][w - 1] : 0u,
                                   w < NWORDS - 1 ? shB[rr + 1][w + 1] : 0u);
        const unsigned hn = horiz3(shB[rr + 2][w],
                                   w > 0 ? shB[rr + 2][w - 1] : 0u,
                                   w < NWORDS - 1 ? shB[rr + 2][w + 1] : 0u);
        const unsigned e = shB[rr + 1][w] & ~(hp & hc & hn);
        shE[rr][w] = e;
        g_edgebits[m][(r0 + rr) * NWORDS + w] = e;
    }
    __syncthreads();

    // per-pixel nearest edge bit in each of the RPB rows (clz/ffs, exact)
    #pragma unroll
    for (int rr = 0; rr < RPB; rr++) {
        const unsigned ew = shE[rr][t];
        float g;
        if ((ew >> k) & 1u) {
            g = 0.0f;
        } else {
            float dl;
            const unsigned lw = (k > 0) ? (ew & ((1u << k) - 1u)) : 0u;
            if (lw) {
                dl = (float)(k - (31 - __clz(lw)));
            } else {
                int tt = t - 1;
                while (tt >= 0 && shE[rr][tt] == 0u) tt--;
                if (tt >= 0) dl = (float)(j - (tt * 32 + (31 - __clz(shE[rr][tt]))));
                else         dl = (float)j + 1e6f;      // reference default, exact fp32
            }
            float dr;
            const unsigned rw = (k < 31) ? (ew & (0xFFFFFFFEu << k)) : 0u;
            if (rw) {
                dr = (float)(__ffs(rw) - 1 - k);
            } else {
                int tt = t + 1;
                while (tt < NWORDS && shE[rr][tt] == 0u) tt++;
                if (tt < NWORDS) dr = (float)((tt * 32 + (__ffs(shE[rr][tt]) - 1)) - j);
                else             dr = 1e6f - (float)j;  // reference default, exact fp32
            }
            g = fminf(fminf(dl, dr), 1e6f);
        }
        g_g2[m][(r0 + rr) * WW + j] = g * g;
    }
}

// ---------------------------------------------------------------------------
// Kernel B: column lower-envelope in SHARED-MEMORY tiles.
// Block = 32 cols x 256 rows, g2 staged with a 32-row halo each side so the
// scan loop hits LDS (29 cyc, conflict-free) instead of ~250-cyc L2 loads.
// Same exact candidates and d^2 >= best prune; pixels needing d beyond the
// staged band (essentially never at this edge density) fall back to global.
// Deterministic in-block tree reduction; no fences, no atomics.
// ---------------------------------------------------------------------------
__global__ void __launch_bounds__(1024) colpass_kernel()
{
    const int c0 = blockIdx.x * CTILE;
    const int t0 = blockIdx.y * RTILE;
    const int m  = blockIdx.z;

    __shared__ float    sh[SROWS][CTILE];
    __shared__ unsigned shM[RTILE];

    const int tid = threadIdx.x;
    const int c   = tid & 31;        // column within tile
    const int rg  = tid >> 5;        // 0..31
    const float* __restrict__ g2 = g_g2[m];

    // stage g2 tile + halo (coalesced: each warp loads one 128B row stripe)
    #pragma unroll
    for (int rr = rg; rr < SROWS; rr += 32) {
        const int row = t0 - HALO + rr;
        sh[rr][c] = (row >= 0 && row < HH) ? g2[row * WW + c0 + c] : 3e37f;
    }
    // one mask word covers the whole 32-col tile for each row
    if (tid < RTILE)
        shM[tid] = g_edgebits[1 - m][(t0 + tid) * NWORDS + (c0 >> 5)];
    __syncthreads();

    float acc = 0.0f;
    #pragma unroll
    for (int q = 0; q < RTILE / 32; q++) {
        const int rl = rg + 32 * q;          // 0..255, row within tile
        if ((shM[rl] >> c) & 1u) {
            const int r  = t0 + rl;          // global row
            const int sr = rl + HALO;        // shared row index (32..287)
            float best = sh[sr][c];
            int d = 1;
            while ((float)(d * d) < best) {  // exact prune: d^2 >= best cannot improve
                const float vu = (sr - d >= 0)
                    ? sh[sr - d][c]
                    : ((r - d >= 0) ? g2[(r - d) * WW + c0 + c] : 3e37f);
                const float vd = (sr + d < SROWS)
                    ? sh[sr + d][c]
                    : ((r + d < HH) ? g2[(r + d) * WW + c0 + c] : 3e37f);
                best = fminf(best, fminf(vu, vd) + (float)(d * d));
                d++;
                if (r - d < 0 && r + d >= HH) break;   // all source rows scanned
            }
            acc += sqrtf(best);
        }
    }

    // deterministic in-block reduction
    float s = acc;
    #pragma unroll
    for (int o = 16; o > 0; o >>= 1) s += __shfl_down_sync(0xffffffffu, s, o);

    __shared__ float warpsum[32];
    if (c == 0) warpsum[rg] = s;
    __syncthreads();

    if (tid < 32) {
        float w = warpsum[tid];
        #pragma unroll
        for (int o = 16; o > 0; o >>= 1) w += __shfl_down_sync(0xffffffffu, w, o);
        if (tid == 0)
            g_blockSums[(m * NB_R + blockIdx.y) * NB_C + blockIdx.x] = w;
    }
}

// ---------------------------------------------------------------------------
// Kernel C: deterministic final reduction + sigmoid.
// ---------------------------------------------------------------------------
__global__ void __launch_bounds__(256) finalize_kernel(float* __restrict__ out)
{
    __shared__ float sh[256];
    sh[threadIdx.x] = g_blockSums[threadIdx.x];   // TOT_B_BLOCKS == 256
    __syncthreads();
    #pragma unroll
    for (int stride = 128; stride > 0; stride >>= 1) {
        if (threadIdx.x < stride) sh[threadIdx.x] += sh[threadIdx.x + stride];
        __syncthreads();
    }
    if (threadIdx.x == 0) {
        const float loss = sh[0] / (2.0f * (float)NPIX);
        out[0] = 1.0f / (1.0f + expf(-loss));
    }
}

// ---------------------------------------------------------------------------
extern "C" void kernel_launch(void* const* d_in, const int* in_sizes, int n_in,
                              void* d_out, int out_size)
{
    const float* preds   = (const float*)d_in[0];
    const float* targets = (const float*)d_in[1];
    float* out = (float*)d_out;
    (void)in_sizes; (void)n_in; (void)out_size;

    dim3 gridA(HH / RPB, 2);
    edges_rowdist_kernel<<<gridA, WW>>>(preds, targets);

    dim3 gridB(NB_C, NB_R, 2);
    colpass_kernel<<<gridB, 1024>>>();

    finalize_kernel<<<1, 256>>>(out);
}